// round 14
// baseline (speedup 1.0000x reference)
#include <cuda_runtime.h>
#include <cuda_bf16.h>
#include <cstdint>
#include <cstring>

// GTN collapses (softmax over singleton axis == 1 -> gtconv == 2*A):
//   H   = 4*(A@A) + I
//   inv = 2 / rowsum(H)   (guarded)
//   out = diag(inv) @ (H @ A)
// Fused persistent kernel (convert -> global barrier -> GEMM1 -> per-stripe
// barrier -> GEMM2). GEMM2 tile (bx,by) depends only on GEMM1 stripe by,
// so barrier #2 is stripe-local (16 CTAs); GEMM2's B fills (g_Abf) are
// issued pre-barrier and fly during the wait.

#define NMAT 2048
static constexpr int BM = 256;
static constexpr int BN = 128;
static constexpr int BK = 32;
static constexpr int STAGES = 4;
static constexpr int KT = NMAT / BK;             // 64
static constexpr int A_STAGE = BM * 64;          // 16KB (64B rows, M-major)
static constexpr int B_STAGE = BK * 256;         // 8KB  (256B k-rows)
static constexpr int SMEM_B_OFF = STAGES * A_STAGE;
static constexpr int SMEM_DYN = STAGES * (A_STAGE + B_STAGE);  // 96KB
static constexpr int NCTA = (NMAT / BN) * (NMAT / BM);         // 128
static constexpr int NSTRIPE = NMAT / BM;                      // 8
static constexpr int STRIPE_CTAS = NMAT / BN;                  // 16

__device__ __nv_bfloat16 g_Abf[(size_t)NMAT * NMAT];
__device__ __nv_bfloat16 g_Hbf[(size_t)NMAT * NMAT];
__device__ float g_rowpart[4][NMAT / BN][NMAT];
__device__ unsigned g_bar_cnt = 0;
__device__ unsigned g_bar_gen = 0;
__device__ unsigned g_sbar_cnt[NSTRIPE] = {};
__device__ unsigned g_sbar_gen[NSTRIPE] = {};

__device__ __forceinline__ uint32_t smem_u32(const void* p) {
    uint32_t a;
    asm("{ .reg .u64 t; cvta.to.shared.u64 t, %1; cvt.u32.u64 %0, t; }" : "=r"(a) : "l"(p));
    return a;
}
#define CP_ASYNC16(dst, src) asm volatile("cp.async.cg.shared.global [%0], [%1], 16;" :: "r"(dst), "l"(src) : "memory")
#define CP_COMMIT()          asm volatile("cp.async.commit_group;" ::: "memory")
#define CP_WAIT2()           asm volatile("cp.async.wait_group 2;" ::: "memory")
#define CP_WAIT0()           asm volatile("cp.async.wait_group 0;" ::: "memory")
#define LDSM_X4(r0, r1, r2, r3, a) \
    asm volatile("ldmatrix.sync.aligned.m8n8.x4.shared.b16 {%0,%1,%2,%3}, [%4];" \
                 : "=r"(r0), "=r"(r1), "=r"(r2), "=r"(r3) : "r"(a))
#define LDSM_X4T(r0, r1, r2, r3, a) \
    asm volatile("ldmatrix.sync.aligned.m8n8.x4.trans.shared.b16 {%0,%1,%2,%3}, [%4];" \
                 : "=r"(r0), "=r"(r1), "=r"(r2), "=r"(r3) : "r"(a))
#define MMA_BF16(c, a, b) \
    asm volatile("mma.sync.aligned.m16n8k16.row.col.f32.bf16.bf16.f32 " \
                 "{%0,%1,%2,%3}, {%4,%5,%6,%7}, {%8,%9}, {%0,%1,%2,%3};" \
                 : "+f"((c)[0]), "+f"((c)[1]), "+f"((c)[2]), "+f"((c)[3]) \
                 : "r"((a)[0]), "r"((a)[1]), "r"((a)[2]), "r"((a)[3]), "r"((b)[0]), "r"((b)[1]))

__device__ __forceinline__ uint32_t swzA(int row, int colb) {
    return (uint32_t)(row * 64 + (colb ^ (((row >> 1) & 3) << 4)));
}
__device__ __forceinline__ uint32_t swzB(int k, int chunk) {
    return (uint32_t)(k * 256 + ((chunk ^ (k & 7)) << 4));
}
__device__ __forceinline__ uint32_t bf2_bits(__nv_bfloat162 v) {
    uint32_t u; memcpy(&u, &v, 4); return u;
}

// Self-resetting barriers (all 128 CTAs co-resident at 1 CTA/SM, grid <= SMs,
// so spinning is deadlock-free; generation captured locally -> replay-safe;
// counter reset by last arriver before the generation bump).
__device__ __forceinline__ void barrier_on(unsigned* cnt, unsigned* gen, unsigned n) {
    __syncthreads();
    if (threadIdx.x == 0) {
        __threadfence();
        volatile unsigned* genp = gen;
        const unsigned g = *genp;
        const unsigned my = atomicAdd(cnt, 1u);
        if (my == n - 1) {
            *(volatile unsigned*)cnt = 0u;
            __threadfence();
            *genp = g + 1u;
        } else {
            while (*genp == g) {}
        }
        __threadfence();
    }
    __syncthreads();
}

// ---------------- GEMM body ----------------
// MODE 0: L = g_Abf ; H = 4D + I -> g_Hbf + row partials
// MODE 1: L = g_Hbf ; out = s_inv[r]*D. B fills issued pre-stripe-barrier.
template <int MODE>
__device__ __forceinline__ void gemm_body(float* __restrict__ Cout,
                                          const uint32_t sb,
                                          const int bx, const int by)
{
    __shared__ float s_inv[BM];

    const int tid = threadIdx.x;
    const int lane = tid & 31;
    const int wid = tid >> 5;
    const int warp_m = wid & 3;
    const int warp_n = wid >> 2;
    const int row0 = by * BM;
    const int col0 = bx * BN;

    const __nv_bfloat16* __restrict__ Lop = (MODE == 0) ? g_Abf : g_Hbf;
    const __nv_bfloat16* __restrict__ Rop = g_Abf;   // B = A k-rows, both modes

    uint32_t abase[2];
#pragma unroll
    for (int st = 0; st < 2; st++)
        abase[st] = swzA(warp_m * 64 + (lane & 15), st * 32 + ((lane >> 4) << 4));

    uint32_t bbase[2][2];
    {
        const int m = lane >> 3, r = lane & 7;
#pragma unroll
        for (int st = 0; st < 2; st++)
#pragma unroll
            for (int np = 0; np < 2; np++)
                bbase[st][np] = swzB(st * 16 + ((m & 1) << 3) + r,
                                     warp_n * 4 + np * 2 + (m >> 1));
    }

    auto fillA = [&](int kt, int s) {
        const uint32_t ab = sb + s * A_STAGE;
#pragma unroll
        for (int i = 0; i < 2; i++) {
            const int ch = i * 512 + tid;
            const int row = ch >> 2, c16 = ch & 3;
            CP_ASYNC16(ab + swzA(row, c16 * 16),
                       Lop + (size_t)(row0 + row) * NMAT + kt * BK + c16 * 8);
        }
    };
    auto fillB = [&](int kt, int s) {
        const uint32_t bb = sb + SMEM_B_OFF + s * B_STAGE;
        const int krow = tid >> 4, c = tid & 15;
        CP_ASYNC16(bb + swzB(krow, c),
                   Rop + (size_t)(kt * BK + krow) * NMAT + col0 + c * 8);
    };

    float acc[4][4][4];
#pragma unroll
    for (int mt = 0; mt < 4; mt++)
#pragma unroll
        for (int nt = 0; nt < 4; nt++)
#pragma unroll
            for (int j = 0; j < 4; j++) acc[mt][nt][j] = 0.f;

    if (MODE == 0) {
        // Joint prologue (both operands ready)
        fillA(0, 0); fillB(0, 0); CP_COMMIT();
        fillA(1, 1); fillB(1, 1); CP_COMMIT();
        fillA(2, 2); fillB(2, 2); CP_COMMIT();
    } else {
        // B operand (g_Abf) is ready pre-barrier: issue its fills now, they
        // fly while we wait for this stripe's GEMM1 producers.
        fillB(0, 0); CP_COMMIT();
        fillB(1, 1); CP_COMMIT();
        fillB(2, 2); CP_COMMIT();

        barrier_on(&g_sbar_cnt[by], &g_sbar_gen[by], STRIPE_CTAS);

        // inv-degree for this CTA's rows (stripe rowparts now visible)
        if (tid < BM) {
            const int r = row0 + tid;
            float d = 0.f;
#pragma unroll
            for (int h = 0; h < 4; h++)
#pragma unroll
                for (int t = 0; t < NMAT / BN; t++) d += g_rowpart[h][t][r];
            if (d <= 1e-10f) d = 1.f;
            s_inv[tid] = 2.f / d;
        }
        // s_inv visibility: the mainloop's __syncthreads() (KT >= 1).

        // H-dependent A fills. Group order B0,B1,B2,A0,A1,A2: wait_group 2
        // at kt=0 drains through A0; per-loop commits keep the invariant.
        fillA(0, 0); CP_COMMIT();
        fillA(1, 1); CP_COMMIT();
        fillA(2, 2); CP_COMMIT();
    }

    for (int kt = 0; kt < KT; kt++) {
        CP_WAIT2();
        __syncthreads();
        const int s = kt & (STAGES - 1);
        const uint32_t ab = sb + s * A_STAGE;
        const uint32_t bb = sb + SMEM_B_OFF + s * B_STAGE;

        uint32_t a[4][4], b[2][4];

        // ---- step 0 ----
#pragma unroll
        for (int mt = 0; mt < 4; mt++)
            LDSM_X4(a[mt][0], a[mt][1], a[mt][2], a[mt][3], ab + abase[0] + mt * 1024);
#pragma unroll
        for (int np = 0; np < 2; np++)
            LDSM_X4T(b[np][0], b[np][1], b[np][2], b[np][3], bb + bbase[0][np]);

        const int f = kt + 3;
        if (f < KT) { fillA(f, f & (STAGES - 1)); fillB(f, f & (STAGES - 1)); }
        CP_COMMIT();

#pragma unroll
        for (int mt = 0; mt < 4; mt++)
#pragma unroll
            for (int nt = 0; nt < 4; nt++) {
                uint32_t bf[2] = {b[nt >> 1][(nt & 1) * 2], b[nt >> 1][(nt & 1) * 2 + 1]};
                MMA_BF16(acc[mt][nt], a[mt], bf);
            }

        // ---- step 1 ----
#pragma unroll
        for (int mt = 0; mt < 4; mt++)
            LDSM_X4(a[mt][0], a[mt][1], a[mt][2], a[mt][3], ab + abase[1] + mt * 1024);
#pragma unroll
        for (int np = 0; np < 2; np++)
            LDSM_X4T(b[np][0], b[np][1], b[np][2], b[np][3], bb + bbase[1][np]);
#pragma unroll
        for (int mt = 0; mt < 4; mt++)
#pragma unroll
            for (int nt = 0; nt < 4; nt++) {
                uint32_t bf[2] = {b[nt >> 1][(nt & 1) * 2], b[nt >> 1][(nt & 1) * 2 + 1]};
                MMA_BF16(acc[mt][nt], a[mt], bf);
            }
    }
    CP_WAIT0();   // drain before smem reuse in the next phase

    // ---------------- epilogue ----------------
#pragma unroll
    for (int mt = 0; mt < 4; mt++) {
        const int rA = row0 + warp_m * 64 + mt * 16 + (lane >> 2);
        const float s0 = (MODE == 0) ? 4.0f : s_inv[rA - row0];
        const float s1 = (MODE == 0) ? 4.0f : s_inv[rA + 8 - row0];
        float rs0 = 0.f, rs1 = 0.f;
#pragma unroll
        for (int nt = 0; nt < 4; nt++) {
            const int c = col0 + warp_n * 32 + nt * 8 + (lane & 3) * 2;
            float v0 = s0 * acc[mt][nt][0];
            float v1 = s0 * acc[mt][nt][1];
            float v2 = s1 * acc[mt][nt][2];
            float v3 = s1 * acc[mt][nt][3];
            if (MODE == 0) {
                if (rA == c)         v0 += 1.0f;
                if (rA == c + 1)     v1 += 1.0f;
                if (rA + 8 == c)     v2 += 1.0f;
                if (rA + 8 == c + 1) v3 += 1.0f;
                rs0 += v0 + v1;
                rs1 += v2 + v3;
                *reinterpret_cast<__nv_bfloat162*>(g_Hbf + (size_t)rA * NMAT + c) =
                    __floats2bfloat162_rn(v0, v1);
                *reinterpret_cast<__nv_bfloat162*>(g_Hbf + (size_t)(rA + 8) * NMAT + c) =
                    __floats2bfloat162_rn(v2, v3);
            } else {
                *reinterpret_cast<float2*>(Cout + (size_t)rA * NMAT + c) = make_float2(v0, v1);
                *reinterpret_cast<float2*>(Cout + (size_t)(rA + 8) * NMAT + c) = make_float2(v2, v3);
            }
        }
        if (MODE == 0) {
            rs0 += __shfl_xor_sync(0xFFFFFFFF, rs0, 1);
            rs0 += __shfl_xor_sync(0xFFFFFFFF, rs0, 2);
            rs1 += __shfl_xor_sync(0xFFFFFFFF, rs1, 1);
            rs1 += __shfl_xor_sync(0xFFFFFFFF, rs1, 2);
            if ((lane & 3) == 0) {
                g_rowpart[warp_n][bx][rA] = rs0;
                g_rowpart[warp_n][bx][rA + 8] = rs1;
            }
        }
    }
}

// ---------------- fused persistent kernel ----------------
__global__ __launch_bounds__(512, 1)
void gtn_fused(const float* __restrict__ A, float* __restrict__ out)
{
    extern __shared__ char dyn_raw[];
    const uint32_t sb = smem_u32(dyn_raw);
    const int bid = blockIdx.x;
    const int tid = threadIdx.x;

    // Phase 0: convert this CTA's 16-row slab of A to bf16 (coalesced).
    {
        const float4* __restrict__ A4 =
            reinterpret_cast<const float4*>(A) + (size_t)bid * 8192;
        uint2* __restrict__ O2 =
            reinterpret_cast<uint2*>(g_Abf) + (size_t)bid * 8192;
#pragma unroll
        for (int i = 0; i < 16; i++) {
            const int idx = i * 512 + tid;
            const float4 v = A4[idx];
            uint2 o;
            o.x = bf2_bits(__floats2bfloat162_rn(v.x, v.y));
            o.y = bf2_bits(__floats2bfloat162_rn(v.z, v.w));
            O2[idx] = o;
        }
    }
    barrier_on(&g_bar_cnt, &g_bar_gen, NCTA);   // g_Abf visible grid-wide

    const int bx = bid & 15, by = bid >> 4;
    gemm_body<0>(out, sb, bx, by);      // H = 4*A@A + I -> g_Hbf + rowparts
    // stripe-local barrier lives inside gemm_body<1>, after its B prefetch
    gemm_body<1>(out, sb, bx, by);      // out = diag(2/deg) @ (H @ A)
}

extern "C" void kernel_launch(void* const* d_in, const int* in_sizes, int n_in,
                              void* d_out, int out_size)
{
    const float* A = (const float*)d_in[0];   // weights unused: softmax over singleton == 1
    float* out = (float*)d_out;

    cudaFuncSetAttribute(gtn_fused, cudaFuncAttributeMaxDynamicSharedMemorySize, SMEM_DYN);
    gtn_fused<<<NCTA, 512, SMEM_DYN>>>(A, out);
}

// round 15
// speedup vs baseline: 1.0025x; 1.0025x over previous
#include <cuda_runtime.h>
#include <cuda_bf16.h>
#include <cstdint>
#include <cstring>

// GTN collapses (softmax over singleton axis == 1 -> gtconv == 2*A):
//   H   = 4*(A@A) + I
//   inv = 2 / rowsum(H)   (guarded)
//   out = diag(inv) @ (H @ A)
// Fused persistent kernel: convert -> global barrier -> GEMM1 -> global
// barrier -> GEMM2. R14 showed skew is CTA-systematic (stripe barriers
// regressed); this round keeps R13's global barrier but issues GEMM2's
// B fills (g_Abf, ready since phase 0) BEFORE the barrier so they fly
// during the spin.

#define NMAT 2048
static constexpr int BM = 256;
static constexpr int BN = 128;
static constexpr int BK = 32;
static constexpr int STAGES = 4;
static constexpr int KT = NMAT / BK;             // 64
static constexpr int A_STAGE = BM * 64;          // 16KB (64B rows, M-major)
static constexpr int B_STAGE = BK * 256;         // 8KB  (256B k-rows)
static constexpr int SMEM_B_OFF = STAGES * A_STAGE;
static constexpr int SMEM_DYN = STAGES * (A_STAGE + B_STAGE);  // 96KB
static constexpr int NCTA = (NMAT / BN) * (NMAT / BM);         // 128

__device__ __nv_bfloat16 g_Abf[(size_t)NMAT * NMAT];
__device__ __nv_bfloat16 g_Hbf[(size_t)NMAT * NMAT];
__device__ float g_rowpart[4][NMAT / BN][NMAT];
__device__ unsigned g_bar_cnt = 0;
__device__ unsigned g_bar_gen = 0;

__device__ __forceinline__ uint32_t smem_u32(const void* p) {
    uint32_t a;
    asm("{ .reg .u64 t; cvta.to.shared.u64 t, %1; cvt.u32.u64 %0, t; }" : "=r"(a) : "l"(p));
    return a;
}
#define CP_ASYNC16(dst, src) asm volatile("cp.async.cg.shared.global [%0], [%1], 16;" :: "r"(dst), "l"(src) : "memory")
#define CP_COMMIT()          asm volatile("cp.async.commit_group;" ::: "memory")
#define CP_WAIT2()           asm volatile("cp.async.wait_group 2;" ::: "memory")
#define CP_WAIT0()           asm volatile("cp.async.wait_group 0;" ::: "memory")
#define LDSM_X4(r0, r1, r2, r3, a) \
    asm volatile("ldmatrix.sync.aligned.m8n8.x4.shared.b16 {%0,%1,%2,%3}, [%4];" \
                 : "=r"(r0), "=r"(r1), "=r"(r2), "=r"(r3) : "r"(a))
#define LDSM_X4T(r0, r1, r2, r3, a) \
    asm volatile("ldmatrix.sync.aligned.m8n8.x4.trans.shared.b16 {%0,%1,%2,%3}, [%4];" \
                 : "=r"(r0), "=r"(r1), "=r"(r2), "=r"(r3) : "r"(a))
#define MMA_BF16(c, a, b) \
    asm volatile("mma.sync.aligned.m16n8k16.row.col.f32.bf16.bf16.f32 " \
                 "{%0,%1,%2,%3}, {%4,%5,%6,%7}, {%8,%9}, {%0,%1,%2,%3};" \
                 : "+f"((c)[0]), "+f"((c)[1]), "+f"((c)[2]), "+f"((c)[3]) \
                 : "r"((a)[0]), "r"((a)[1]), "r"((a)[2]), "r"((a)[3]), "r"((b)[0]), "r"((b)[1]))

__device__ __forceinline__ uint32_t swzA(int row, int colb) {
    return (uint32_t)(row * 64 + (colb ^ (((row >> 1) & 3) << 4)));
}
__device__ __forceinline__ uint32_t swzB(int k, int chunk) {
    return (uint32_t)(k * 256 + ((chunk ^ (k & 7)) << 4));
}
__device__ __forceinline__ uint32_t bf2_bits(__nv_bfloat162 v) {
    uint32_t u; memcpy(&u, &v, 4); return u;
}

// Self-resetting global barrier (128 CTAs co-resident at 1 CTA/SM: safe).
__device__ __forceinline__ void grid_barrier() {
    __syncthreads();
    if (threadIdx.x == 0) {
        __threadfence();
        volatile unsigned* genp = &g_bar_gen;
        const unsigned g = *genp;
        const unsigned my = atomicAdd(&g_bar_cnt, 1u);
        if (my == NCTA - 1) {
            *(volatile unsigned*)&g_bar_cnt = 0u;
            __threadfence();
            *genp = g + 1u;
        } else {
            while (*genp == g) {}
        }
        __threadfence();
    }
    __syncthreads();
}

// ---------------- GEMM body ----------------
// MODE 0: L = g_Abf ; H = 4D + I -> g_Hbf + row partials
// MODE 1: L = g_Hbf ; out = s_inv[r]*D. B fills issued pre-barrier; the
//         global barrier (waiting for ALL GEMM1 tiles) lives inside.
template <int MODE>
__device__ __forceinline__ void gemm_body(float* __restrict__ Cout,
                                          const uint32_t sb,
                                          const int bx, const int by)
{
    __shared__ float s_inv[BM];

    const int tid = threadIdx.x;
    const int lane = tid & 31;
    const int wid = tid >> 5;
    const int warp_m = wid & 3;
    const int warp_n = wid >> 2;
    const int row0 = by * BM;
    const int col0 = bx * BN;

    const __nv_bfloat16* __restrict__ Lop = (MODE == 0) ? g_Abf : g_Hbf;
    const __nv_bfloat16* __restrict__ Rop = g_Abf;   // B = A k-rows, both modes

    uint32_t abase[2];
#pragma unroll
    for (int st = 0; st < 2; st++)
        abase[st] = swzA(warp_m * 64 + (lane & 15), st * 32 + ((lane >> 4) << 4));

    uint32_t bbase[2][2];
    {
        const int m = lane >> 3, r = lane & 7;
#pragma unroll
        for (int st = 0; st < 2; st++)
#pragma unroll
            for (int np = 0; np < 2; np++)
                bbase[st][np] = swzB(st * 16 + ((m & 1) << 3) + r,
                                     warp_n * 4 + np * 2 + (m >> 1));
    }

    auto fillA = [&](int kt, int s) {
        const uint32_t ab = sb + s * A_STAGE;
#pragma unroll
        for (int i = 0; i < 2; i++) {
            const int ch = i * 512 + tid;
            const int row = ch >> 2, c16 = ch & 3;
            CP_ASYNC16(ab + swzA(row, c16 * 16),
                       Lop + (size_t)(row0 + row) * NMAT + kt * BK + c16 * 8);
        }
    };
    auto fillB = [&](int kt, int s) {
        const uint32_t bb = sb + SMEM_B_OFF + s * B_STAGE;
        const int krow = tid >> 4, c = tid & 15;
        CP_ASYNC16(bb + swzB(krow, c),
                   Rop + (size_t)(kt * BK + krow) * NMAT + col0 + c * 8);
    };

    float acc[4][4][4];
#pragma unroll
    for (int mt = 0; mt < 4; mt++)
#pragma unroll
        for (int nt = 0; nt < 4; nt++)
#pragma unroll
            for (int j = 0; j < 4; j++) acc[mt][nt][j] = 0.f;

    if (MODE == 0) {
        fillA(0, 0); fillB(0, 0); CP_COMMIT();
        fillA(1, 1); fillB(1, 1); CP_COMMIT();
        fillA(2, 2); fillB(2, 2); CP_COMMIT();
    } else {
        // B (g_Abf) is ready: its fills fly during the barrier spin.
        fillB(0, 0); CP_COMMIT();
        fillB(1, 1); CP_COMMIT();
        fillB(2, 2); CP_COMMIT();

        grid_barrier();            // all GEMM1 tiles (g_Hbf, rowparts) visible

        if (tid < BM) {
            const int r = row0 + tid;
            float d = 0.f;
#pragma unroll
            for (int h = 0; h < 4; h++)
#pragma unroll
                for (int t = 0; t < NMAT / BN; t++) d += g_rowpart[h][t][r];
            if (d <= 1e-10f) d = 1.f;
            s_inv[tid] = 2.f / d;
        }
        // s_inv visibility: the mainloop's __syncthreads() (KT >= 1).

        // H-dependent A fills. Group order B0,B1,B2,A0,A1,A2: wait_group 2
        // at kt=0 drains through A0 (stage-s B always completes before
        // stage-s A is needed).
        fillA(0, 0); CP_COMMIT();
        fillA(1, 1); CP_COMMIT();
        fillA(2, 2); CP_COMMIT();
    }

    for (int kt = 0; kt < KT; kt++) {
        CP_WAIT2();
        __syncthreads();
        const int s = kt & (STAGES - 1);
        const uint32_t ab = sb + s * A_STAGE;
        const uint32_t bb = sb + SMEM_B_OFF + s * B_STAGE;

        uint32_t a[4][4], b[2][4];

        // ---- step 0 ----
#pragma unroll
        for (int mt = 0; mt < 4; mt++)
            LDSM_X4(a[mt][0], a[mt][1], a[mt][2], a[mt][3], ab + abase[0] + mt * 1024);
#pragma unroll
        for (int np = 0; np < 2; np++)
            LDSM_X4T(b[np][0], b[np][1], b[np][2], b[np][3], bb + bbase[0][np]);

        const int f = kt + 3;
        if (f < KT) { fillA(f, f & (STAGES - 1)); fillB(f, f & (STAGES - 1)); }
        CP_COMMIT();

#pragma unroll
        for (int mt = 0; mt < 4; mt++)
#pragma unroll
            for (int nt = 0; nt < 4; nt++) {
                uint32_t bf[2] = {b[nt >> 1][(nt & 1) * 2], b[nt >> 1][(nt & 1) * 2 + 1]};
                MMA_BF16(acc[mt][nt], a[mt], bf);
            }

        // ---- step 1 ----
#pragma unroll
        for (int mt = 0; mt < 4; mt++)
            LDSM_X4(a[mt][0], a[mt][1], a[mt][2], a[mt][3], ab + abase[1] + mt * 1024);
#pragma unroll
        for (int np = 0; np < 2; np++)
            LDSM_X4T(b[np][0], b[np][1], b[np][2], b[np][3], bb + bbase[1][np]);
#pragma unroll
        for (int mt = 0; mt < 4; mt++)
#pragma unroll
            for (int nt = 0; nt < 4; nt++) {
                uint32_t bf[2] = {b[nt >> 1][(nt & 1) * 2], b[nt >> 1][(nt & 1) * 2 + 1]};
                MMA_BF16(acc[mt][nt], a[mt], bf);
            }
    }
    CP_WAIT0();   // drain before smem reuse in the next phase

    // ---------------- epilogue ----------------
#pragma unroll
    for (int mt = 0; mt < 4; mt++) {
        const int rA = row0 + warp_m * 64 + mt * 16 + (lane >> 2);
        const float s0 = (MODE == 0) ? 4.0f : s_inv[rA - row0];
        const float s1 = (MODE == 0) ? 4.0f : s_inv[rA + 8 - row0];
        float rs0 = 0.f, rs1 = 0.f;
#pragma unroll
        for (int nt = 0; nt < 4; nt++) {
            const int c = col0 + warp_n * 32 + nt * 8 + (lane & 3) * 2;
            float v0 = s0 * acc[mt][nt][0];
            float v1 = s0 * acc[mt][nt][1];
            float v2 = s1 * acc[mt][nt][2];
            float v3 = s1 * acc[mt][nt][3];
            if (MODE == 0) {
                if (rA == c)         v0 += 1.0f;
                if (rA == c + 1)     v1 += 1.0f;
                if (rA + 8 == c)     v2 += 1.0f;
                if (rA + 8 == c + 1) v3 += 1.0f;
                rs0 += v0 + v1;
                rs1 += v2 + v3;
                *reinterpret_cast<__nv_bfloat162*>(g_Hbf + (size_t)rA * NMAT + c) =
                    __floats2bfloat162_rn(v0, v1);
                *reinterpret_cast<__nv_bfloat162*>(g_Hbf + (size_t)(rA + 8) * NMAT + c) =
                    __floats2bfloat162_rn(v2, v3);
            } else {
                *reinterpret_cast<float2*>(Cout + (size_t)rA * NMAT + c) = make_float2(v0, v1);
                *reinterpret_cast<float2*>(Cout + (size_t)(rA + 8) * NMAT + c) = make_float2(v2, v3);
            }
        }
        if (MODE == 0) {
            rs0 += __shfl_xor_sync(0xFFFFFFFF, rs0, 1);
            rs0 += __shfl_xor_sync(0xFFFFFFFF, rs0, 2);
            rs1 += __shfl_xor_sync(0xFFFFFFFF, rs1, 1);
            rs1 += __shfl_xor_sync(0xFFFFFFFF, rs1, 2);
            if ((lane & 3) == 0) {
                g_rowpart[warp_n][bx][rA] = rs0;
                g_rowpart[warp_n][bx][rA + 8] = rs1;
            }
        }
    }
}

// ---------------- fused persistent kernel ----------------
__global__ __launch_bounds__(512, 1)
void gtn_fused(const float* __restrict__ A, float* __restrict__ out)
{
    extern __shared__ char dyn_raw[];
    const uint32_t sb = smem_u32(dyn_raw);
    const int bid = blockIdx.x;
    const int tid = threadIdx.x;

    // Phase 0: convert this CTA's 16-row slab of A to bf16 (coalesced).
    {
        const float4* __restrict__ A4 =
            reinterpret_cast<const float4*>(A) + (size_t)bid * 8192;
        uint2* __restrict__ O2 =
            reinterpret_cast<uint2*>(g_Abf) + (size_t)bid * 8192;
#pragma unroll
        for (int i = 0; i < 16; i++) {
            const int idx = i * 512 + tid;
            const float4 v = A4[idx];
            uint2 o;
            o.x = bf2_bits(__floats2bfloat162_rn(v.x, v.y));
            o.y = bf2_bits(__floats2bfloat162_rn(v.z, v.w));
            O2[idx] = o;
        }
    }
    grid_barrier();                     // g_Abf visible grid-wide

    const int bx = bid & 15, by = bid >> 4;
    gemm_body<0>(out, sb, bx, by);      // H = 4*A@A + I -> g_Hbf + rowparts
    // global barrier #2 lives inside gemm_body<1>, after its B prefetch
    gemm_body<1>(out, sb, bx, by);      // out = diag(2/deg) @ (H @ A)
}

extern "C" void kernel_launch(void* const* d_in, const int* in_sizes, int n_in,
                              void* d_out, int out_size)
{
    const float* A = (const float*)d_in[0];   // weights unused: softmax over singleton == 1
    float* out = (float*)d_out;

    cudaFuncSetAttribute(gtn_fused, cudaFuncAttributeMaxDynamicSharedMemorySize, SMEM_DYN);
    gtn_fused<<<NCTA, 512, SMEM_DYN>>>(A, out);
}

// round 16
// speedup vs baseline: 1.0203x; 1.0177x over previous
#include <cuda_runtime.h>
#include <cuda_bf16.h>
#include <cstdint>
#include <cstring>

// GTN collapses (softmax over singleton axis == 1 -> gtconv == 2*A):
//   H   = 4*(A@A) + I
//   inv = 2 / rowsum(H)   (guarded)
//   out = diag(inv) @ (H @ A)
// Fused persistent kernel (R13 skeleton: convert -> global barrier -> GEMM1
// -> global barrier -> GEMM2). This round: 2-tile k-groups on a 6-stage ring
// (144KB smem) -> HALF the wait_group+__syncthreads count in the mainloop.

#define NMAT 2048
static constexpr int BM = 256;
static constexpr int BN = 128;
static constexpr int BK = 32;
static constexpr int KT = NMAT / BK;             // 64 tiles, 32 groups of 2
static constexpr int NSLOT = 6;                  // 3 group-slots x 2 tiles
static constexpr int A_STAGE = BM * 64;          // 16KB (64B rows, M-major)
static constexpr int B_STAGE = BK * 256;         // 8KB  (256B k-rows)
static constexpr int SMEM_B_OFF = NSLOT * A_STAGE;             // 96KB
static constexpr int SMEM_DYN = NSLOT * (A_STAGE + B_STAGE);   // 144KB
static constexpr int NCTA = (NMAT / BN) * (NMAT / BM);         // 128

__device__ __nv_bfloat16 g_Abf[(size_t)NMAT * NMAT];
__device__ __nv_bfloat16 g_Hbf[(size_t)NMAT * NMAT];
__device__ float g_rowpart[4][NMAT / BN][NMAT];
__device__ unsigned g_bar_cnt = 0;
__device__ unsigned g_bar_gen = 0;

__device__ __forceinline__ uint32_t smem_u32(const void* p) {
    uint32_t a;
    asm("{ .reg .u64 t; cvta.to.shared.u64 t, %1; cvt.u32.u64 %0, t; }" : "=r"(a) : "l"(p));
    return a;
}
#define CP_ASYNC16(dst, src) asm volatile("cp.async.cg.shared.global [%0], [%1], 16;" :: "r"(dst), "l"(src) : "memory")
#define CP_COMMIT()          asm volatile("cp.async.commit_group;" ::: "memory")
#define CP_WAIT1()           asm volatile("cp.async.wait_group 1;" ::: "memory")
#define CP_WAIT0()           asm volatile("cp.async.wait_group 0;" ::: "memory")
#define LDSM_X4(r0, r1, r2, r3, a) \
    asm volatile("ldmatrix.sync.aligned.m8n8.x4.shared.b16 {%0,%1,%2,%3}, [%4];" \
                 : "=r"(r0), "=r"(r1), "=r"(r2), "=r"(r3) : "r"(a))
#define LDSM_X4T(r0, r1, r2, r3, a) \
    asm volatile("ldmatrix.sync.aligned.m8n8.x4.trans.shared.b16 {%0,%1,%2,%3}, [%4];" \
                 : "=r"(r0), "=r"(r1), "=r"(r2), "=r"(r3) : "r"(a))
#define MMA_BF16(c, a, b) \
    asm volatile("mma.sync.aligned.m16n8k16.row.col.f32.bf16.bf16.f32 " \
                 "{%0,%1,%2,%3}, {%4,%5,%6,%7}, {%8,%9}, {%0,%1,%2,%3};" \
                 : "+f"((c)[0]), "+f"((c)[1]), "+f"((c)[2]), "+f"((c)[3]) \
                 : "r"((a)[0]), "r"((a)[1]), "r"((a)[2]), "r"((a)[3]), "r"((b)[0]), "r"((b)[1]))

__device__ __forceinline__ uint32_t swzA(int row, int colb) {
    return (uint32_t)(row * 64 + (colb ^ (((row >> 1) & 3) << 4)));
}
__device__ __forceinline__ uint32_t swzB(int k, int chunk) {
    return (uint32_t)(k * 256 + ((chunk ^ (k & 7)) << 4));
}
__device__ __forceinline__ uint32_t bf2_bits(__nv_bfloat162 v) {
    uint32_t u; memcpy(&u, &v, 4); return u;
}
// stage slot for k-tile t: group (t/2) -> slot pair ((t/2)%3), tile parity picks half
__device__ __forceinline__ int tile_slot(int t) {
    return 2 * ((t >> 1) % 3) + (t & 1);
}

// Self-resetting global barrier (128 CTAs co-resident at 1 CTA/SM: safe).
__device__ __forceinline__ void grid_barrier() {
    __syncthreads();
    if (threadIdx.x == 0) {
        __threadfence();
        volatile unsigned* genp = &g_bar_gen;
        const unsigned g = *genp;
        const unsigned my = atomicAdd(&g_bar_cnt, 1u);
        if (my == NCTA - 1) {
            *(volatile unsigned*)&g_bar_cnt = 0u;
            __threadfence();
            *genp = g + 1u;
        } else {
            while (*genp == g) {}
        }
        __threadfence();
    }
    __syncthreads();
}

// ---------------- GEMM body ----------------
// MODE 0: L = g_Abf ; H = 4D + I -> g_Hbf + row partials
// MODE 1: L = g_Hbf ; out = s_inv[r]*D (inv computed after barrier, caller-side)
template <int MODE>
__device__ __forceinline__ void gemm_body(float* __restrict__ Cout,
                                          const uint32_t sb,
                                          const int bx, const int by)
{
    __shared__ float s_inv[BM];

    const int tid = threadIdx.x;
    const int lane = tid & 31;
    const int wid = tid >> 5;
    const int warp_m = wid & 3;
    const int warp_n = wid >> 2;
    const int row0 = by * BM;
    const int col0 = bx * BN;

    const __nv_bfloat16* __restrict__ Lop = (MODE == 0) ? g_Abf : g_Hbf;
    const __nv_bfloat16* __restrict__ Rop = g_Abf;   // B = A k-rows, both modes

    uint32_t abase[2];
#pragma unroll
    for (int st = 0; st < 2; st++)
        abase[st] = swzA(warp_m * 64 + (lane & 15), st * 32 + ((lane >> 4) << 4));

    uint32_t bbase[2][2];
    {
        const int m = lane >> 3, r = lane & 7;
#pragma unroll
        for (int st = 0; st < 2; st++)
#pragma unroll
            for (int np = 0; np < 2; np++)
                bbase[st][np] = swzB(st * 16 + ((m & 1) << 3) + r,
                                     warp_n * 4 + np * 2 + (m >> 1));
    }

    // fill k-tile t into its slot: A 1024 chunks (2/thread) + B 512 (1/thread)
    auto fill = [&](int t) {
        const int slot = tile_slot(t);
        const uint32_t ab = sb + slot * A_STAGE;
        const uint32_t bb = sb + SMEM_B_OFF + slot * B_STAGE;
#pragma unroll
        for (int i = 0; i < 2; i++) {
            const int ch = i * 512 + tid;
            const int row = ch >> 2, c16 = ch & 3;
            CP_ASYNC16(ab + swzA(row, c16 * 16),
                       Lop + (size_t)(row0 + row) * NMAT + t * BK + c16 * 8);
        }
        {
            const int krow = tid >> 4, c = tid & 15;
            CP_ASYNC16(bb + swzB(krow, c),
                       Rop + (size_t)(t * BK + krow) * NMAT + col0 + c * 8);
        }
    };

    float acc[4][4][4];
#pragma unroll
    for (int mt = 0; mt < 4; mt++)
#pragma unroll
        for (int nt = 0; nt < 4; nt++)
#pragma unroll
            for (int j = 0; j < 4; j++) acc[mt][nt][j] = 0.f;

    // Prologue: groups 0 (tiles 0,1) and 1 (tiles 2,3)
    fill(0); fill(1); CP_COMMIT();
    fill(2); fill(3); CP_COMMIT();

    if (MODE == 1 && tid < BM) {
        const int r = row0 + tid;
        float d = 0.f;
#pragma unroll
        for (int h = 0; h < 4; h++)
#pragma unroll
            for (int t = 0; t < NMAT / BN; t++) d += g_rowpart[h][t][r];
        if (d <= 1e-10f) d = 1.f;
        s_inv[tid] = 2.f / d;
    }
    // s_inv visibility: the mainloop's __syncthreads() (KT >= 2).

    // One MMA step for tile slot (consumes step st of that slot's stages)
    auto do_tile_step = [&](const uint32_t ab, const uint32_t bb, int st) {
        uint32_t a[4][4], b[2][4];
#pragma unroll
        for (int mt = 0; mt < 4; mt++)
            LDSM_X4(a[mt][0], a[mt][1], a[mt][2], a[mt][3], ab + abase[st] + mt * 1024);
#pragma unroll
        for (int np = 0; np < 2; np++)
            LDSM_X4T(b[np][0], b[np][1], b[np][2], b[np][3], bb + bbase[st][np]);
#pragma unroll
        for (int mt = 0; mt < 4; mt++)
#pragma unroll
            for (int nt = 0; nt < 4; nt++) {
                uint32_t bf[2] = {b[nt >> 1][(nt & 1) * 2], b[nt >> 1][(nt & 1) * 2 + 1]};
                MMA_BF16(acc[mt][nt], a[mt], bf);
            }
    };

    // Mainloop: 32 iterations of 2 tiles; ONE wait + ONE syncthreads each.
    for (int kt = 0; kt < KT; kt += 2) {
        CP_WAIT1();               // group kt/2 resident (kt/2+1 may be in flight)
        __syncthreads();

        const int s0 = tile_slot(kt);
        const int s1 = tile_slot(kt + 1);
        const uint32_t ab0 = sb + s0 * A_STAGE;
        const uint32_t bb0 = sb + SMEM_B_OFF + s0 * B_STAGE;
        const uint32_t ab1 = sb + s1 * A_STAGE;
        const uint32_t bb1 = sb + SMEM_B_OFF + s1 * B_STAGE;

        // tile kt, step 0
        do_tile_step(ab0, bb0, 0);

        // fills for group kt/2 + 2 (writes a slot-pair neither current nor next)
        if (kt + 4 < KT) { fill(kt + 4); fill(kt + 5); }
        CP_COMMIT();              // commit every iteration to keep group counting

        do_tile_step(ab0, bb0, 1);        // tile kt, step 1
        do_tile_step(ab1, bb1, 0);        // tile kt+1, step 0
        do_tile_step(ab1, bb1, 1);        // tile kt+1, step 1
    }
    CP_WAIT0();   // drain before smem reuse in the next phase

    // ---------------- epilogue ----------------
#pragma unroll
    for (int mt = 0; mt < 4; mt++) {
        const int rA = row0 + warp_m * 64 + mt * 16 + (lane >> 2);
        const float s0 = (MODE == 0) ? 4.0f : s_inv[rA - row0];
        const float s1 = (MODE == 0) ? 4.0f : s_inv[rA + 8 - row0];
        float rs0 = 0.f, rs1 = 0.f;
#pragma unroll
        for (int nt = 0; nt < 4; nt++) {
            const int c = col0 + warp_n * 32 + nt * 8 + (lane & 3) * 2;
            float v0 = s0 * acc[mt][nt][0];
            float v1 = s0 * acc[mt][nt][1];
            float v2 = s1 * acc[mt][nt][2];
            float v3 = s1 * acc[mt][nt][3];
            if (MODE == 0) {
                if (rA == c)         v0 += 1.0f;
                if (rA == c + 1)     v1 += 1.0f;
                if (rA + 8 == c)     v2 += 1.0f;
                if (rA + 8 == c + 1) v3 += 1.0f;
                rs0 += v0 + v1;
                rs1 += v2 + v3;
                *reinterpret_cast<__nv_bfloat162*>(g_Hbf + (size_t)rA * NMAT + c) =
                    __floats2bfloat162_rn(v0, v1);
                *reinterpret_cast<__nv_bfloat162*>(g_Hbf + (size_t)(rA + 8) * NMAT + c) =
                    __floats2bfloat162_rn(v2, v3);
            } else {
                *reinterpret_cast<float2*>(Cout + (size_t)rA * NMAT + c) = make_float2(v0, v1);
                *reinterpret_cast<float2*>(Cout + (size_t)(rA + 8) * NMAT + c) = make_float2(v2, v3);
            }
        }
        if (MODE == 0) {
            rs0 += __shfl_xor_sync(0xFFFFFFFF, rs0, 1);
            rs0 += __shfl_xor_sync(0xFFFFFFFF, rs0, 2);
            rs1 += __shfl_xor_sync(0xFFFFFFFF, rs1, 1);
            rs1 += __shfl_xor_sync(0xFFFFFFFF, rs1, 2);
            if ((lane & 3) == 0) {
                g_rowpart[warp_n][bx][rA] = rs0;
                g_rowpart[warp_n][bx][rA + 8] = rs1;
            }
        }
    }
}

// ---------------- fused persistent kernel ----------------
__global__ __launch_bounds__(512, 1)
void gtn_fused(const float* __restrict__ A, float* __restrict__ out)
{
    extern __shared__ char dyn_raw[];
    const uint32_t sb = smem_u32(dyn_raw);
    const int bid = blockIdx.x;
    const int tid = threadIdx.x;

    // Phase 0: convert this CTA's 16-row slab of A to bf16 (coalesced).
    {
        const float4* __restrict__ A4 =
            reinterpret_cast<const float4*>(A) + (size_t)bid * 8192;
        uint2* __restrict__ O2 =
            reinterpret_cast<uint2*>(g_Abf) + (size_t)bid * 8192;
#pragma unroll
        for (int i = 0; i < 16; i++) {
            const int idx = i * 512 + tid;
            const float4 v = A4[idx];
            uint2 o;
            o.x = bf2_bits(__floats2bfloat162_rn(v.x, v.y));
            o.y = bf2_bits(__floats2bfloat162_rn(v.z, v.w));
            O2[idx] = o;
        }
    }
    grid_barrier();                     // g_Abf visible grid-wide

    const int bx = bid & 15, by = bid >> 4;
    gemm_body<0>(out, sb, bx, by);      // H = 4*A@A + I -> g_Hbf + rowparts
    grid_barrier();                     // g_Hbf + g_rowpart visible
    gemm_body<1>(out, sb, bx, by);      // out = diag(2/deg) @ (H @ A)
}

extern "C" void kernel_launch(void* const* d_in, const int* in_sizes, int n_in,
                              void* d_out, int out_size)
{
    const float* A = (const float*)d_in[0];   // weights unused: softmax over singleton == 1
    float* out = (float*)d_out;

    cudaFuncSetAttribute(gtn_fused, cudaFuncAttributeMaxDynamicSharedMemorySize, SMEM_DYN);
    gtn_fused<<<NCTA, 512, SMEM_DYN>>>(A, out);
}